// round 5
// baseline (speedup 1.0000x reference)
#include <cuda_runtime.h>
#include <cuda_bf16.h>
#include <cstdint>

// ---------------------------------------------------------------------------
// Compile-time Cl(4,1) Cayley structure tensors for the sandwich M X ~M.
// Generated as constexpr so all blade indices fold to compile-time constants
// -> register-resident multivectors, pure FFMA chain, no dynamic indexing.
// ---------------------------------------------------------------------------

struct Term { int a; int b; int c; float s; };
struct Tab80 { Term t[80]; };

__host__ __device__ constexpr int pc5(int x) {
    int c = 0;
    for (int i = 0; i < 6; i++) c += (x >> i) & 1;
    return c;
}

__host__ __device__ constexpr int blade_mul_out(int a, int b) { return a ^ b; }

__host__ __device__ constexpr float blade_mul_sign(int a, int b) {
    int s = 0;
    int t = a >> 1;
    while (t) { s += pc5(t & b); t >>= 1; }
    float sign = (s & 1) ? -1.0f : 1.0f;
    if ((a & b) & 16) sign = -sign;  // e5^2 = -1
    return sign;
}

// T1: even[16] * g1[5] -> odd[16]   (M X)
__host__ __device__ constexpr Tab80 gen_T1() {
    Tab80 r{};
    int even[16] = {}, odd[16] = {};
    int ne = 0, no = 0;
    for (int b = 0; b < 32; b++) {
        if ((pc5(b) & 1) == 0) even[ne++] = b; else odd[no++] = b;
    }
    int g1[5] = {1, 2, 4, 8, 16};
    int oidx[32] = {};
    for (int i = 0; i < 16; i++) oidx[odd[i]] = i;
    int k = 0;
    for (int ie = 0; ie < 16; ie++) {
        for (int ip = 0; ip < 5; ip++) {
            int c = blade_mul_out(even[ie], g1[ip]);
            float s = blade_mul_sign(even[ie], g1[ip]);
            r.t[k].a = ie;
            r.t[k].b = ip;
            r.t[k].c = oidx[c];
            r.t[k].s = s;
            k++;
        }
    }
    return r;
}

// T2: odd[16] * reverse(even[16]) -> grade-1[5]
__host__ __device__ constexpr Tab80 gen_T2() {
    Tab80 r{};
    int even[16] = {}, odd[16] = {};
    int ne = 0, no = 0;
    for (int b = 0; b < 32; b++) {
        if ((pc5(b) & 1) == 0) even[ne++] = b; else odd[no++] = b;
    }
    int g1[5] = {1, 2, 4, 8, 16};
    int k = 0;
    for (int io = 0; io < 16; io++) {
        for (int ie = 0; ie < 16; ie++) {
            int c = blade_mul_out(odd[io], even[ie]);
            int gq = -1;
            for (int q = 0; q < 5; q++) if (g1[q] == c) gq = q;
            if (gq >= 0) {
                float s = blade_mul_sign(odd[io], even[ie]);
                int g = pc5(even[ie]);
                float rs = (((g * (g - 1) / 2) & 1) != 0) ? -1.0f : 1.0f;
                r.t[k].a = io;
                r.t[k].b = ie;
                r.t[k].c = gq;
                r.t[k].s = s * rs;
                k++;
            }
        }
    }
    return r;
}

// ---------------------------------------------------------------------------
// Core per-point sandwich: encode -> M X -> (M X)~M -> decode.
// All indices compile-time constants -> pure register FFMA chain.
// ---------------------------------------------------------------------------
__device__ __forceinline__ void sandwich_one(const float* __restrict__ v,
                                             float x0, float x1, float x2,
                                             float* __restrict__ o)
{
    float hs = 0.5f * (x0 * x0 + x1 * x1 + x2 * x2);
    float p[5] = {x0, x1, x2, hs - 0.5f, hs + 0.5f};

    constexpr Tab80 t1 = gen_T1();
    float mx[16] = {0, 0, 0, 0, 0, 0, 0, 0, 0, 0, 0, 0, 0, 0, 0, 0};
#pragma unroll
    for (int k = 0; k < 80; k++) {
        mx[t1.t[k].c] += t1.t[k].s * v[t1.t[k].a] * p[t1.t[k].b];
    }

    constexpr Tab80 t2 = gen_T2();
    float q[5] = {0, 0, 0, 0, 0};
#pragma unroll
    for (int k = 0; k < 80; k++) {
        q[t2.t[k].c] += t2.t[k].s * mx[t2.t[k].a] * v[t2.t[k].b];
    }

    float inv = 1.0f / (q[4] - q[3]);
    o[0] = q[0] * inv;
    o[1] = q[1] * inv;
    o[2] = q[2] * inv;
}

// ---------------------------------------------------------------------------
// Main kernel: 4 points per thread, all loads/stores 128-bit.
//   per thread: 16 LDG.128 (versors) + 3 LDG.128 (x, 12 floats = 4 points)
//               -> MLP = 19 front-batched loads
//   stores: 3 STG.128
// ---------------------------------------------------------------------------
__global__ void __launch_bounds__(256)
cga_sandwich4_kernel(const float4* __restrict__ versor4,
                     const float4* __restrict__ x4,
                     float4* __restrict__ out4,
                     int n4)   // number of 4-point groups
{
    int i = blockIdx.x * blockDim.x + threadIdx.x;
    if (i >= n4) return;

    // ---- front-batched loads: 16 + 3 = 19 independent LDG.128 ----
    float vv[64];
    const float4* vp = versor4 + (size_t)i * 16;
#pragma unroll
    for (int k = 0; k < 16; k++) {
        float4 t = vp[k];
        vv[4 * k + 0] = t.x;
        vv[4 * k + 1] = t.y;
        vv[4 * k + 2] = t.z;
        vv[4 * k + 3] = t.w;
    }

    float xx[12];
    const float4* xp = x4 + (size_t)i * 3;
#pragma unroll
    for (int k = 0; k < 3; k++) {
        float4 t = xp[k];
        xx[4 * k + 0] = t.x;
        xx[4 * k + 1] = t.y;
        xx[4 * k + 2] = t.z;
        xx[4 * k + 3] = t.w;
    }

    // ---- compute 4 points ----
    float oo[12];
#pragma unroll
    for (int p = 0; p < 4; p++) {
        sandwich_one(vv + 16 * p, xx[3 * p + 0], xx[3 * p + 1], xx[3 * p + 2],
                     oo + 3 * p);
    }

    // ---- 3 STG.128 ----
    float4* op = out4 + (size_t)i * 3;
#pragma unroll
    for (int k = 0; k < 3; k++) {
        float4 t;
        t.x = oo[4 * k + 0];
        t.y = oo[4 * k + 1];
        t.z = oo[4 * k + 2];
        t.w = oo[4 * k + 3];
        op[k] = t;
    }
}

// Scalar tail kernel (n not divisible by 4) — same math, 1 point/thread.
__global__ void __launch_bounds__(256)
cga_sandwich_tail_kernel(const float* __restrict__ versor,
                         const float* __restrict__ x,
                         float* __restrict__ out,
                         int start, int n)
{
    int i = start + blockIdx.x * blockDim.x + threadIdx.x;
    if (i >= n) return;

    float v[16];
    const float* vp = versor + (size_t)i * 16;
#pragma unroll
    for (int k = 0; k < 16; k++) v[k] = vp[k];

    const float* xp = x + (size_t)i * 3;
    float o[3];
    sandwich_one(v, xp[0], xp[1], xp[2], o);

    float* op = out + (size_t)i * 3;
    op[0] = o[0];
    op[1] = o[1];
    op[2] = o[2];
}

extern "C" void kernel_launch(void* const* d_in, const int* in_sizes, int n_in,
                              void* d_out, int out_size)
{
    const float* versor = (const float*)d_in[0];  // (N, 16) f32
    const float* x      = (const float*)d_in[1];  // (N, 3)  f32
    float* out          = (float*)d_out;          // (N, 3)  f32

    int n = in_sizes[0] / 16;
    int n4 = n / 4;           // full 4-point groups
    int tail = n - n4 * 4;

    if (n4 > 0) {
        int threads = 256;
        int blocks = (n4 + threads - 1) / threads;
        cga_sandwich4_kernel<<<blocks, threads>>>(
            (const float4*)versor, (const float4*)x, (float4*)out, n4);
    }
    if (tail > 0) {
        cga_sandwich_tail_kernel<<<1, 256>>>(versor, x, out, n4 * 4, n);
    }
}

// round 8
// speedup vs baseline: 1.2427x; 1.2427x over previous
#include <cuda_runtime.h>
#include <cuda_bf16.h>
#include <cstdint>

// ---------------------------------------------------------------------------
// Compile-time Cl(4,1) Cayley structure tensors for the sandwich M X ~M.
// Generated as constexpr so all blade indices fold to compile-time constants
// -> register-resident multivectors, pure FFMA chain, no dynamic indexing.
// ---------------------------------------------------------------------------

struct Term { int a; int b; int c; float s; };
struct Tab80 { Term t[80]; };

__host__ __device__ constexpr int pc5(int x) {
    int c = 0;
    for (int i = 0; i < 6; i++) c += (x >> i) & 1;
    return c;
}

__host__ __device__ constexpr int blade_mul_out(int a, int b) { return a ^ b; }

__host__ __device__ constexpr float blade_mul_sign(int a, int b) {
    int s = 0;
    int t = a >> 1;
    while (t) { s += pc5(t & b); t >>= 1; }
    float sign = (s & 1) ? -1.0f : 1.0f;
    if ((a & b) & 16) sign = -sign;  // e5^2 = -1
    return sign;
}

// T1: even[16] * g1[5] -> odd[16]   (M X)
__host__ __device__ constexpr Tab80 gen_T1() {
    Tab80 r{};
    int even[16] = {}, odd[16] = {};
    int ne = 0, no = 0;
    for (int b = 0; b < 32; b++) {
        if ((pc5(b) & 1) == 0) even[ne++] = b; else odd[no++] = b;
    }
    int g1[5] = {1, 2, 4, 8, 16};
    int oidx[32] = {};
    for (int i = 0; i < 16; i++) oidx[odd[i]] = i;
    int k = 0;
    for (int ie = 0; ie < 16; ie++) {
        for (int ip = 0; ip < 5; ip++) {
            int c = blade_mul_out(even[ie], g1[ip]);
            float s = blade_mul_sign(even[ie], g1[ip]);
            r.t[k].a = ie;
            r.t[k].b = ip;
            r.t[k].c = oidx[c];
            r.t[k].s = s;
            k++;
        }
    }
    return r;
}

// T2: odd[16] * reverse(even[16]) -> grade-1[5]
__host__ __device__ constexpr Tab80 gen_T2() {
    Tab80 r{};
    int even[16] = {}, odd[16] = {};
    int ne = 0, no = 0;
    for (int b = 0; b < 32; b++) {
        if ((pc5(b) & 1) == 0) even[ne++] = b; else odd[no++] = b;
    }
    int g1[5] = {1, 2, 4, 8, 16};
    int k = 0;
    for (int io = 0; io < 16; io++) {
        for (int ie = 0; ie < 16; ie++) {
            int c = blade_mul_out(odd[io], even[ie]);
            int gq = -1;
            for (int q = 0; q < 5; q++) if (g1[q] == c) gq = q;
            if (gq >= 0) {
                float s = blade_mul_sign(odd[io], even[ie]);
                int g = pc5(even[ie]);
                float rs = (((g * (g - 1) / 2) & 1) != 0) ? -1.0f : 1.0f;
                r.t[k].a = io;
                r.t[k].b = ie;
                r.t[k].c = gq;
                r.t[k].s = s * rs;
                k++;
            }
        }
    }
    return r;
}

// ---------------------------------------------------------------------------
// Core per-point sandwich: encode -> M X -> (M X)~M -> decode.
// ---------------------------------------------------------------------------
__device__ __forceinline__ void sandwich_one(const float* __restrict__ v,
                                             float x0, float x1, float x2,
                                             float* __restrict__ o)
{
    float hs = 0.5f * (x0 * x0 + x1 * x1 + x2 * x2);
    float p[5] = {x0, x1, x2, hs - 0.5f, hs + 0.5f};

    constexpr Tab80 t1 = gen_T1();
    float mx[16] = {0, 0, 0, 0, 0, 0, 0, 0, 0, 0, 0, 0, 0, 0, 0, 0};
#pragma unroll
    for (int k = 0; k < 80; k++) {
        mx[t1.t[k].c] += t1.t[k].s * v[t1.t[k].a] * p[t1.t[k].b];
    }

    constexpr Tab80 t2 = gen_T2();
    float q[5] = {0, 0, 0, 0, 0};
#pragma unroll
    for (int k = 0; k < 80; k++) {
        q[t2.t[k].c] += t2.t[k].s * mx[t2.t[k].a] * v[t2.t[k].b];
    }

    float inv = 1.0f / (q[4] - q[3]);
    o[0] = q[0] * inv;
    o[1] = q[1] * inv;
    o[2] = q[2] * inv;
}

// ---------------------------------------------------------------------------
// Main kernel: 1 point per thread, FULL blocks only (grid covers n_main).
// x and out are staged through shared memory so ALL global traffic is
// 128-bit coalesced:
//   per block (256 points): 1024 LDG.128 versor + 192 LDG.128 x
//                           + 192 STG.128 out
// smem reads stride-3 (gcd(3,32)=1 -> conflict-free).
// ---------------------------------------------------------------------------
constexpr int BLK = 256;

__global__ void __launch_bounds__(BLK)
cga_sandwich_smem_kernel(const float4* __restrict__ versor4,
                         const float4* __restrict__ x4,
                         float4* __restrict__ out4)
{
    __shared__ float sx[BLK * 3];
    __shared__ float so[BLK * 3];

    int tid = threadIdx.x;
    int i = blockIdx.x * BLK + tid;

    // ---- stage x: 192 LDG.128 cover 256 points' coordinates ----
    if (tid < (BLK * 3) / 4) {
        float4 t = x4[(size_t)blockIdx.x * ((BLK * 3) / 4) + tid];
        reinterpret_cast<float4*>(sx)[tid] = t;
    }

    // ---- versor: 4 LDG.128 per thread (independent of smem stage) ----
    const float4* vp = versor4 + (size_t)i * 4;
    float4 a0 = vp[0];
    float4 a1 = vp[1];
    float4 a2 = vp[2];
    float4 a3 = vp[3];
    float v[16] = {a0.x, a0.y, a0.z, a0.w,
                   a1.x, a1.y, a1.z, a1.w,
                   a2.x, a2.y, a2.z, a2.w,
                   a3.x, a3.y, a3.z, a3.w};

    __syncthreads();

    // ---- read own coords (stride-3, conflict-free) ----
    float x0 = sx[3 * tid + 0];
    float x1 = sx[3 * tid + 1];
    float x2 = sx[3 * tid + 2];

    float o[3];
    sandwich_one(v, x0, x1, x2, o);

    so[3 * tid + 0] = o[0];
    so[3 * tid + 1] = o[1];
    so[3 * tid + 2] = o[2];

    __syncthreads();

    // ---- write out: 192 STG.128 per block ----
    if (tid < (BLK * 3) / 4) {
        float4 t = reinterpret_cast<const float4*>(so)[tid];
        out4[(size_t)blockIdx.x * ((BLK * 3) / 4) + tid] = t;
    }
}

// Scalar tail kernel (points not covered by full blocks).
__global__ void __launch_bounds__(BLK)
cga_sandwich_tail_kernel(const float* __restrict__ versor,
                         const float* __restrict__ x,
                         float* __restrict__ out,
                         int start, int n)
{
    int i = start + blockIdx.x * blockDim.x + threadIdx.x;
    if (i >= n) return;

    float v[16];
    const float* vp = versor + (size_t)i * 16;
#pragma unroll
    for (int k = 0; k < 16; k++) v[k] = vp[k];

    const float* xp = x + (size_t)i * 3;
    float o[3];
    sandwich_one(v, xp[0], xp[1], xp[2], o);

    float* op = out + (size_t)i * 3;
    op[0] = o[0];
    op[1] = o[1];
    op[2] = o[2];
}

extern "C" void kernel_launch(void* const* d_in, const int* in_sizes, int n_in,
                              void* d_out, int out_size)
{
    const float* versor = (const float*)d_in[0];  // (N, 16) f32
    const float* x      = (const float*)d_in[1];  // (N, 3)  f32
    float* out          = (float*)d_out;          // (N, 3)  f32

    int n = in_sizes[0] / 16;
    int n_blocks = n / BLK;           // full blocks
    int n_main = n_blocks * BLK;
    int tail = n - n_main;

    if (n_blocks > 0) {
        cga_sandwich_smem_kernel<<<n_blocks, BLK>>>(
            (const float4*)versor, (const float4*)x, (float4*)out);
    }
    if (tail > 0) {
        cga_sandwich_tail_kernel<<<(tail + BLK - 1) / BLK, BLK>>>(
            versor, x, out, n_main, n);
    }
}

// round 10
// speedup vs baseline: 1.3309x; 1.0710x over previous
#include <cuda_runtime.h>
#include <cuda_bf16.h>
#include <cstdint>

// ---------------------------------------------------------------------------
// Compile-time Cl(4,1) Cayley structure tensors for the sandwich M X ~M.
// Generated as constexpr so all blade indices fold to compile-time constants
// -> register-resident multivectors, pure FFMA chain, no dynamic indexing.
// ---------------------------------------------------------------------------

struct Term { int a; int b; int c; float s; };
struct Tab80 { Term t[80]; };

__host__ __device__ constexpr int pc5(int x) {
    int c = 0;
    for (int i = 0; i < 6; i++) c += (x >> i) & 1;
    return c;
}

__host__ __device__ constexpr int blade_mul_out(int a, int b) { return a ^ b; }

__host__ __device__ constexpr float blade_mul_sign(int a, int b) {
    int s = 0;
    int t = a >> 1;
    while (t) { s += pc5(t & b); t >>= 1; }
    float sign = (s & 1) ? -1.0f : 1.0f;
    if ((a & b) & 16) sign = -sign;  // e5^2 = -1
    return sign;
}

// T1: even[16] * g1[5] -> odd[16]   (M X)
__host__ __device__ constexpr Tab80 gen_T1() {
    Tab80 r{};
    int even[16] = {}, odd[16] = {};
    int ne = 0, no = 0;
    for (int b = 0; b < 32; b++) {
        if ((pc5(b) & 1) == 0) even[ne++] = b; else odd[no++] = b;
    }
    int g1[5] = {1, 2, 4, 8, 16};
    int oidx[32] = {};
    for (int i = 0; i < 16; i++) oidx[odd[i]] = i;
    int k = 0;
    for (int ie = 0; ie < 16; ie++) {
        for (int ip = 0; ip < 5; ip++) {
            int c = blade_mul_out(even[ie], g1[ip]);
            float s = blade_mul_sign(even[ie], g1[ip]);
            r.t[k].a = ie;
            r.t[k].b = ip;
            r.t[k].c = oidx[c];
            r.t[k].s = s;
            k++;
        }
    }
    return r;
}

// T2: odd[16] * reverse(even[16]) -> grade-1[5]
__host__ __device__ constexpr Tab80 gen_T2() {
    Tab80 r{};
    int even[16] = {}, odd[16] = {};
    int ne = 0, no = 0;
    for (int b = 0; b < 32; b++) {
        if ((pc5(b) & 1) == 0) even[ne++] = b; else odd[no++] = b;
    }
    int g1[5] = {1, 2, 4, 8, 16};
    int k = 0;
    for (int io = 0; io < 16; io++) {
        for (int ie = 0; ie < 16; ie++) {
            int c = blade_mul_out(odd[io], even[ie]);
            int gq = -1;
            for (int q = 0; q < 5; q++) if (g1[q] == c) gq = q;
            if (gq >= 0) {
                float s = blade_mul_sign(odd[io], even[ie]);
                int g = pc5(even[ie]);
                float rs = (((g * (g - 1) / 2) & 1) != 0) ? -1.0f : 1.0f;
                r.t[k].a = io;
                r.t[k].b = ie;
                r.t[k].c = gq;
                r.t[k].s = s * rs;
                k++;
            }
        }
    }
    return r;
}

// ---------------------------------------------------------------------------
// Kernel: one thread per point.  Pure HBM stream, zero reuse -> all global
// accesses use streaming (evict-first) cache ops.
// ---------------------------------------------------------------------------
__global__ void __launch_bounds__(256)
cga_sandwich_kernel(const float* __restrict__ versor,
                    const float* __restrict__ x,
                    float* __restrict__ out,
                    int n)
{
    int i = blockIdx.x * blockDim.x + threadIdx.x;
    if (i >= n) return;

    // ---- load versor: 16 f32 via 4x LDG.128.CS (64B, warp-contiguous) ----
    const float4* v4 = reinterpret_cast<const float4*>(versor) + (size_t)i * 4;
    float4 a0 = __ldcs(v4 + 0);
    float4 a1 = __ldcs(v4 + 1);
    float4 a2 = __ldcs(v4 + 2);
    float4 a3 = __ldcs(v4 + 3);

    // ---- load x (3 f32, warp covers contiguous 384B) ----
    const float* xp = x + (size_t)i * 3;
    float x0 = __ldcs(xp + 0);
    float x1 = __ldcs(xp + 1);
    float x2 = __ldcs(xp + 2);

    float v[16] = {a0.x, a0.y, a0.z, a0.w,
                   a1.x, a1.y, a1.z, a1.w,
                   a2.x, a2.y, a2.z, a2.w,
                   a3.x, a3.y, a3.z, a3.w};

    // ---- CGA encode: P = (x, 0.5|x|^2 - 0.5, 0.5|x|^2 + 0.5) ----
    float hs = 0.5f * (x0 * x0 + x1 * x1 + x2 * x2);
    float p[5] = {x0, x1, x2, hs - 0.5f, hs + 0.5f};

    // ---- mx = M X (even * grade1 -> odd, 80 FFMA) ----
    constexpr Tab80 t1 = gen_T1();
    float mx[16] = {0, 0, 0, 0, 0, 0, 0, 0, 0, 0, 0, 0, 0, 0, 0, 0};
#pragma unroll
    for (int k = 0; k < 80; k++) {
        mx[t1.t[k].c] += t1.t[k].s * v[t1.t[k].a] * p[t1.t[k].b];
    }

    // ---- q = (M X) ~M, grade-1 part (80 FFMA) ----
    constexpr Tab80 t2 = gen_T2();
    float q[5] = {0, 0, 0, 0, 0};
#pragma unroll
    for (int k = 0; k < 80; k++) {
        q[t2.t[k].c] += t2.t[k].s * mx[t2.t[k].a] * v[t2.t[k].b];
    }

    // ---- CGA decode: xyz * rcp(q_e5 - q_e4)  (MUFU.RCP, ~2^-22 rel err) ----
    float inv = __fdividef(1.0f, q[4] - q[3]);
    float* op = out + (size_t)i * 3;
    __stcs(op + 0, q[0] * inv);
    __stcs(op + 1, q[1] * inv);
    __stcs(op + 2, q[2] * inv);
}

extern "C" void kernel_launch(void* const* d_in, const int* in_sizes, int n_in,
                              void* d_out, int out_size)
{
    const float* versor = (const float*)d_in[0];  // (N, 16) f32
    const float* x      = (const float*)d_in[1];  // (N, 3)  f32
    float* out          = (float*)d_out;          // (N, 3)  f32

    int n = in_sizes[0] / 16;
    int threads = 256;
    int blocks = (n + threads - 1) / threads;
    cga_sandwich_kernel<<<blocks, threads>>>(versor, x, out, n);
}